// round 9
// baseline (speedup 1.0000x reference)
#include <cuda_runtime.h>
#include <cstdint>

// Problem constants
#define B_    8
#define C_    64
#define H_    256
#define W_    256
#define HW_   65536
#define OC_   64
#define P_    16
#define CU_   48
#define OUTC_ 112

// ---------------- device globals -------------------------------------------
__device__ float d_act[B_ * C_];
__device__ int   d_sel[B_ * P_];
__device__ int   d_unsel[B_ * CU_];

// ---------------- f32x2 helpers --------------------------------------------
__device__ __forceinline__ unsigned long long pack2(float lo, float hi) {
    unsigned long long r;
    asm("mov.b64 %0, {%1, %2};" : "=l"(r)
        : "r"(__float_as_uint(lo)), "r"(__float_as_uint(hi)));
    return r;
}
__device__ __forceinline__ void unpack2(unsigned long long v, float& lo, float& hi) {
    unsigned int a, b;
    asm("mov.b64 {%0, %1}, %2;" : "=r"(a), "=r"(b) : "l"(v));
    lo = __uint_as_float(a);
    hi = __uint_as_float(b);
}
__device__ __forceinline__ unsigned long long fma2(unsigned long long a,
                                                   unsigned long long b,
                                                   unsigned long long c) {
    unsigned long long d;
    asm("fma.rn.f32x2 %0, %1, %2, %3;" : "=l"(d) : "l"(a), "l"(b), "l"(c));
    return d;
}

// ---------------- kernel 1: per-channel min/max + histogram + entropy -------
// 1024 threads/block, one block per (b,c); 2 blocks/SM -> pass 2 L2-resident.
__global__ void __launch_bounds__(1024, 2)
channel_stats_kernel(const float* __restrict__ x) {
    const int bc  = blockIdx.x;
    const int tid = threadIdx.x;
    const int lane = tid & 31, wid = tid >> 5;
    const float4* xp = reinterpret_cast<const float4*>(x) + (size_t)bc * (HW_ / 4);

    // ---- pass 1: min / max ----
    float mn = 3.402823466e38f, mx = -3.402823466e38f;
    for (int i = tid; i < HW_ / 4; i += 1024) {
        float4 v = xp[i];
        mn = fminf(mn, fminf(fminf(v.x, v.y), fminf(v.z, v.w)));
        mx = fmaxf(mx, fmaxf(fmaxf(v.x, v.y), fmaxf(v.z, v.w)));
    }
    #pragma unroll
    for (int off = 16; off > 0; off >>= 1) {
        mn = fminf(mn, __shfl_xor_sync(0xffffffffu, mn, off));
        mx = fmaxf(mx, __shfl_xor_sync(0xffffffffu, mx, off));
    }
    __shared__ float smn[32], smx[32];
    __shared__ float s_mn, s_rng, s_scale;
    if (lane == 0) { smn[wid] = mn; smx[wid] = mx; }
    __syncthreads();
    if (tid == 0) {
        float m = smn[0], M = smx[0];
        #pragma unroll
        for (int i = 1; i < 32; i++) { m = fminf(m, smn[i]); M = fmaxf(M, smx[i]); }
        s_mn = m;
        float rng = __fadd_rn(__fsub_rn(M, m), 1e-8f);  // (max-min)+eps, IEEE rn
        s_rng = rng;
        s_scale = __fdiv_rn(256.0f, rng);
    }
    __syncthreads();

    // ---- pass 2: histogram (8 smem copies; 4 warps share a copy) ----
    __shared__ int h[8][256];
    for (int i = tid; i < 8 * 256; i += 1024) ((int*)h)[i] = 0;
    __syncthreads();
    const float mnv = s_mn, rng = s_rng, sc = s_scale;
    int* hw = h[wid & 7];
    for (int i = tid; i < HW_ / 4; i += 1024) {
        float4 v = xp[i];
        float vals[4] = { v.x, v.y, v.z, v.w };
        #pragma unroll
        for (int k = 0; k < 4; k++) {
            float t = __fsub_rn(vals[k], mnv);
            float a = __fmul_rn(t, sc);                 // fast approx of (t/rng)*256
            int bin = (int)a;
            float fr = a - (float)bin;
            float band = __fmaf_rn(4e-7f, a, 1e-6f);
            if (fr < band || fr > 1.0f - band) {        // near a bin edge: exact path
                a = __fmul_rn(__fdiv_rn(t, rng), 256.0f);
                bin = (int)a;
            }
            if (bin > 255) bin = 255;
            atomicAdd(&hw[bin], 1);
        }
    }
    __syncthreads();

    // ---- entropy ----
    __shared__ float hf[256], red[256];
    if (tid < 256) {
        int c = 0;
        #pragma unroll
        for (int w2 = 0; w2 < 8; w2++) c += h[w2][tid];
        hf[tid] = (float)c + 1e-8f;
        red[tid] = hf[tid];
    }
    __syncthreads();
    for (int st = 128; st > 0; st >>= 1) {
        if (tid < st) red[tid] += red[tid + st];
        __syncthreads();
    }
    __shared__ float s_tot;
    if (tid == 0) s_tot = red[0];
    __syncthreads();
    if (tid < 256) {
        float p = hf[tid] / s_tot;
        red[tid] = p * logf(p + 1e-8f);
    }
    __syncthreads();
    for (int st = 128; st > 0; st >>= 1) {
        if (tid < st) red[tid] += red[tid + st];
        __syncthreads();
    }
    if (tid == 0) d_act[bc] = -red[0];
}

// ---------------- kernel 2: top-16 (desc, ties -> lowest idx) + unselected --
__global__ void topk_kernel() {
    int b = threadIdx.x;
    if (b >= B_) return;
    float a[C_];
    bool  m[C_];
    for (int c = 0; c < C_; c++) { a[c] = d_act[b * C_ + c]; m[c] = false; }
    for (int k = 0; k < P_; k++) {
        float best = -3.402823466e38f;
        int bi = 0;
        for (int c = 0; c < C_; c++)
            if (!m[c] && a[c] > best) { best = a[c]; bi = c; }
        d_sel[b * P_ + k] = bi;
        m[bi] = true;
    }
    int j = 0;
    for (int c = 0; c < C_; c++)
        if (!m[c]) d_unsel[b * CU_ + (j++)] = c;
}

// ---------------- kernel 3 (fused): FFMA2 conv + untouched copy -------------
// Grid = 1408 blocks of 256 threads, interleaved 3 copy : 8 conv per 11.
// Conv tile: 8 rows x 64 cols, all 64 ocs. Thread = (ocg=tid>>6 -> 16 ocs as
// 8 f32x2 pairs) x (slot=tid&63 -> col; 8 pixels down the rows).
// acc[8 pix][8 ocpair] = 128 regs; PIX=8 x OCP=8 -> 64 FMA2 per 24 aux instrs.
#define XS_RS   66
#define XS_CH   660                       // 10 rows * 66
#define XS_FL   10560                     // 16 ch * 660
#define WPK     4608                      // 144 * 32 oc-pairs (ULL words)
#define SM_W_BYTES  (WPK * 8)             // 36864
#define SM_TOTAL    (SM_W_BYTES + XS_FL * 4)  // 79104

#define NCOPY   (B_ * CU_)                // 384
#define NCONV   (B_ * 32 * 4)             // 1024
#define GRID_   (NCOPY + NCONV)           // 1408 = 128 * (3 + 8)

__global__ void __launch_bounds__(256)
conv_copy_kernel(const float* __restrict__ x, const float* __restrict__ wgt,
                 const float* __restrict__ bias, float* __restrict__ out) {
    const int tid = threadIdx.x;
    const int per = blockIdx.x / 11;
    const int ph  = blockIdx.x % 11;

    // ---------- copy path (3 of every 11 blocks) ----------
    if (ph < 3) {
        int id = per * 3 + ph;            // 0..383
        int j = id % CU_, b = id / CU_;
        int ch = d_unsel[b * CU_ + j];
        const float4* src = reinterpret_cast<const float4*>(x)
                            + ((size_t)(b * C_ + ch)) * (HW_ / 4);
        float4* dst = reinterpret_cast<float4*>(out)
                      + ((size_t)(b * OUTC_ + OC_ + j)) * (HW_ / 4);
        #pragma unroll 4
        for (int i = tid; i < HW_ / 4; i += 256) dst[i] = src[i];
        return;
    }

    // ---------- conv path ----------
    extern __shared__ char smc[];
    unsigned long long* swpk = (unsigned long long*)smc;       // [144][32]
    float* xs = (float*)(smc + SM_W_BYTES);                    // [16][10][66]
    __shared__ int ssel[P_];

    const int cid = per * 8 + (ph - 3);   // 0..1023
    const int b  = cid >> 7;
    const int rem = cid & 127;
    const int r0 = (rem >> 2) * 8;
    const int c0 = (rem & 3) * 64;

    if (tid < P_) ssel[tid] = d_sel[b * P_ + tid];
    // pack weights into {oc_even, oc_odd} f32x2 words: swpk[t][o]
    for (int idx = tid; idx < WPK; idx += 256) {
        int t = idx >> 5, o = idx & 31;
        swpk[idx] = pack2(wgt[(2 * o) * 144 + t], wgt[(2 * o + 1) * 144 + t]);
    }
    __syncthreads();                       // ssel ready

    // stage 16 channels x 10 rows x 66 cols (halo, zero-padded)
    for (int idx = tid; idx < XS_FL; idx += 256) {
        int p = idx / XS_CH;
        int r2 = idx - p * XS_CH;
        int rr = r2 / XS_RS;
        int cc = r2 - rr * XS_RS;
        int gr = r0 + rr - 1, gc = c0 + cc - 1;
        float v = 0.0f;
        if ((unsigned)gr < 256u && (unsigned)gc < 256u)
            v = x[(((size_t)(b * C_ + ssel[p])) << 16) + (gr << 8) + gc];
        xs[idx] = v;
    }
    __syncthreads();

    const int ocg  = tid >> 6;            // 0..3 -> 16 ocs
    const int slot = tid & 63;            // col within tile

    unsigned long long acc[8][8];
    #pragma unroll
    for (int o = 0; o < 8; o++) {
        int oc0 = ocg * 16 + 2 * o;
        unsigned long long bz = pack2(__ldg(&bias[oc0]), __ldg(&bias[oc0 + 1]));
        #pragma unroll
        for (int pr = 0; pr < 8; pr++) acc[pr][o] = bz;
    }

    const float* xb = xs + slot;
    for (int p = 0; p < 16; p++) {
        const float* xp2 = xb + p * XS_CH;
        #pragma unroll
        for (int kh = 0; kh < 3; kh++) {
            #pragma unroll
            for (int kw = 0; kw < 3; kw++) {
                unsigned long long xd[8];
                #pragma unroll
                for (int pr = 0; pr < 8; pr++) {
                    float v = xp2[(pr + kh) * XS_RS + kw];
                    xd[pr] = pack2(v, v);
                }
                const unsigned long long* wr =
                    swpk + (((p * 9 + kh * 3 + kw) << 5) + (ocg << 3));
                #pragma unroll
                for (int o = 0; o < 8; o++) {
                    unsigned long long wv = wr[o];
                    #pragma unroll
                    for (int pr = 0; pr < 8; pr++)
                        acc[pr][o] = fma2(xd[pr], wv, acc[pr][o]);
                }
            }
        }
    }

    // store: lane(slot) -> consecutive cols, fully coalesced 32-float rows
    float* ob = out + (((size_t)(b * OUTC_)) << 16) + (r0 << 8) + c0 + slot;
    #pragma unroll
    for (int o = 0; o < 8; o++) {
        int oc0 = ocg * 16 + 2 * o;
        float* o0 = ob + ((size_t)oc0 << 16);
        float* o1 = o0 + HW_;
        #pragma unroll
        for (int pr = 0; pr < 8; pr++) {
            float lo, hi;
            unpack2(acc[pr][o], lo, hi);
            o0[pr << 8] = lo;
            o1[pr << 8] = hi;
        }
    }
}

// ---------------- launch ----------------------------------------------------
extern "C" void kernel_launch(void* const* d_in, const int* in_sizes, int n_in,
                              void* d_out, int out_size) {
    (void)in_sizes; (void)n_in; (void)out_size;
    const float* x    = (const float*)d_in[0];
    const float* wgt  = (const float*)d_in[1];
    const float* bias = (const float*)d_in[2];
    float* out = (float*)d_out;

    cudaFuncSetAttribute(conv_copy_kernel,
                         cudaFuncAttributeMaxDynamicSharedMemorySize, SM_TOTAL);

    channel_stats_kernel<<<B_ * C_, 1024>>>(x);
    topk_kernel<<<1, 8>>>();
    conv_copy_kernel<<<GRID_, 256, SM_TOTAL>>>(x, wgt, bias, out);
}

// round 10
// speedup vs baseline: 1.6152x; 1.6152x over previous
#include <cuda_runtime.h>
#include <cuda_bf16.h>
#include <cstdint>

// Problem constants
#define B_    8
#define C_    64
#define H_    256
#define W_    256
#define HW_   65536
#define OC_   64
#define P_    16
#define CU_   48
#define OUTC_ 112

// ---------------- device globals -------------------------------------------
__device__ float d_act[B_ * C_];
__device__ int   d_sel[B_ * P_];
__device__ int   d_unsel[B_ * CU_];
// packed weights: [chunk 9][p2 8][n pad 72] u32 = (bf16 p=2*p2, bf16 p=2*p2+1)
__device__ uint32_t d_whi[9 * 8 * 72];
__device__ uint32_t d_wlo[9 * 8 * 72];

// ---------------- kernel 0: weight split + fragment-layout pack -------------
__global__ void prep_W_kernel(const float* __restrict__ wgt) {
    for (int i = threadIdx.x; i < 9 * 8 * 72; i += 256) {
        int chunk = i / 576;
        int rem   = i % 576;
        int p2    = rem / 72;
        int n     = rem % 72;
        uint32_t hi = 0, lo = 0;
        if (n < 64) {
            float w0 = wgt[n * 144 + (2 * p2) * 9 + chunk];
            float w1 = wgt[n * 144 + (2 * p2 + 1) * 9 + chunk];
            __nv_bfloat16 h0 = __float2bfloat16_rn(w0);
            __nv_bfloat16 h1 = __float2bfloat16_rn(w1);
            __nv_bfloat16 l0 = __float2bfloat16_rn(w0 - __bfloat162float(h0));
            __nv_bfloat16 l1 = __float2bfloat16_rn(w1 - __bfloat162float(h1));
            hi = (uint32_t)__bfloat16_as_ushort(h0) | ((uint32_t)__bfloat16_as_ushort(h1) << 16);
            lo = (uint32_t)__bfloat16_as_ushort(l0) | ((uint32_t)__bfloat16_as_ushort(l1) << 16);
        }
        d_whi[i] = hi;
        d_wlo[i] = lo;
    }
}

// ---------------- kernel 1: per-channel min/max + histogram + entropy -------
__global__ void __launch_bounds__(1024, 2)
channel_stats_kernel(const float* __restrict__ x) {
    const int bc  = blockIdx.x;
    const int tid = threadIdx.x;
    const int lane = tid & 31, wid = tid >> 5;
    const float4* xp = reinterpret_cast<const float4*>(x) + (size_t)bc * (HW_ / 4);

    float mn = 3.402823466e38f, mx = -3.402823466e38f;
    for (int i = tid; i < HW_ / 4; i += 1024) {
        float4 v = xp[i];
        mn = fminf(mn, fminf(fminf(v.x, v.y), fminf(v.z, v.w)));
        mx = fmaxf(mx, fmaxf(fmaxf(v.x, v.y), fmaxf(v.z, v.w)));
    }
    #pragma unroll
    for (int off = 16; off > 0; off >>= 1) {
        mn = fminf(mn, __shfl_xor_sync(0xffffffffu, mn, off));
        mx = fmaxf(mx, __shfl_xor_sync(0xffffffffu, mx, off));
    }
    __shared__ float smn[32], smx[32];
    __shared__ float s_mn, s_rng, s_scale;
    if (lane == 0) { smn[wid] = mn; smx[wid] = mx; }
    __syncthreads();
    if (tid == 0) {
        float m = smn[0], M = smx[0];
        #pragma unroll
        for (int i = 1; i < 32; i++) { m = fminf(m, smn[i]); M = fmaxf(M, smx[i]); }
        s_mn = m;
        float rng = __fadd_rn(__fsub_rn(M, m), 1e-8f);
        s_rng = rng;
        s_scale = __fdiv_rn(256.0f, rng);
    }
    __syncthreads();

    __shared__ int h[8][256];
    for (int i = tid; i < 8 * 256; i += 1024) ((int*)h)[i] = 0;
    __syncthreads();
    const float mnv = s_mn, rng = s_rng, sc = s_scale;
    int* hw = h[wid & 7];
    for (int i = tid; i < HW_ / 4; i += 1024) {
        float4 v = xp[i];
        float vals[4] = { v.x, v.y, v.z, v.w };
        #pragma unroll
        for (int k = 0; k < 4; k++) {
            float t = __fsub_rn(vals[k], mnv);
            float a = __fmul_rn(t, sc);
            int bin = (int)a;
            float fr = a - (float)bin;
            float band = __fmaf_rn(4e-7f, a, 1e-6f);
            if (fr < band || fr > 1.0f - band) {
                a = __fmul_rn(__fdiv_rn(t, rng), 256.0f);   // exact path near edges
                bin = (int)a;
            }
            if (bin > 255) bin = 255;
            atomicAdd(&hw[bin], 1);
        }
    }
    __syncthreads();

    __shared__ float hf[256], red[256];
    if (tid < 256) {
        int c = 0;
        #pragma unroll
        for (int w2 = 0; w2 < 8; w2++) c += h[w2][tid];
        hf[tid] = (float)c + 1e-8f;
        red[tid] = hf[tid];
    }
    __syncthreads();
    for (int st = 128; st > 0; st >>= 1) {
        if (tid < st) red[tid] += red[tid + st];
        __syncthreads();
    }
    __shared__ float s_tot;
    if (tid == 0) s_tot = red[0];
    __syncthreads();
    if (tid < 256) {
        float p = hf[tid] / s_tot;
        red[tid] = p * logf(p + 1e-8f);
    }
    __syncthreads();
    for (int st = 128; st > 0; st >>= 1) {
        if (tid < st) red[tid] += red[tid + st];
        __syncthreads();
    }
    if (tid == 0) d_act[bc] = -red[0];
}

// ---------------- kernel 2: top-16 + unselected -----------------------------
__global__ void topk_kernel() {
    int b = threadIdx.x;
    if (b >= B_) return;
    float a[C_];
    bool  m[C_];
    for (int c = 0; c < C_; c++) { a[c] = d_act[b * C_ + c]; m[c] = false; }
    for (int k = 0; k < P_; k++) {
        float best = -3.402823466e38f;
        int bi = 0;
        for (int c = 0; c < C_; c++)
            if (!m[c] && a[c] > best) { best = a[c]; bi = c; }
        d_sel[b * P_ + k] = bi;
        m[bi] = true;
    }
    int j = 0;
    for (int c = 0; c < C_; c++)
        if (!m[c]) d_unsel[b * CU_ + (j++)] = c;
}

// ---------------- kernel 3 (fused): mma.sync bf16x3 conv + untouched copy ---
// Grid = 2432 blocks of 256 threads: per 19-block group, 3 copy + 16 conv.
// Conv tile: M = 256 pixels (2 rows x 128 cols), N = 64 ocs, K = 144.
// K split into 9 chunks of 16 channels, chunk = kh*3+kw.
// smem: w blobs [9][8][72] u32 (hi+lo), strip [4 rows][132 cols][18 ch-halves].
#define WS_U32   (9 * 8 * 72)                 // 5184 u32 per blob
#define XS_HALF  (4 * 132 * 18)               // 9504 halves per blob
#define SM_WHI   0
#define SM_WLO   (WS_U32 * 4)                 // 20736
#define SM_XHI   (2 * WS_U32 * 4)             // 41472
#define SM_XLO   (SM_XHI + XS_HALF * 2)       // 60480
#define SM_TOTAL (SM_XLO + XS_HALF * 2)       // 79488

#define NCONV 2048
#define NCOPY (B_ * CU_)                      // 384
#define GRID_ (NCONV + NCOPY)                 // 2432 = 128 * 19

__device__ __forceinline__ void mma_bf16(float* d, const uint32_t* a, const uint32_t* b) {
    asm volatile(
        "mma.sync.aligned.m16n8k16.row.col.f32.bf16.bf16.f32 "
        "{%0,%1,%2,%3}, {%4,%5,%6,%7}, {%8,%9}, {%0,%1,%2,%3};\n"
        : "+f"(d[0]), "+f"(d[1]), "+f"(d[2]), "+f"(d[3])
        : "r"(a[0]), "r"(a[1]), "r"(a[2]), "r"(a[3]), "r"(b[0]), "r"(b[1]));
}

__global__ void __launch_bounds__(256)
conv_copy_kernel(const float* __restrict__ x, const float* __restrict__ bias,
                 float* __restrict__ out) {
    const int tid  = threadIdx.x;
    const int grp  = blockIdx.x / 19;
    const int slot = blockIdx.x % 19;

    // ---------- copy path (3 of every 19 blocks) ----------
    if (slot < 3) {
        int id = grp * 3 + slot;              // 0..383
        int j = id % CU_, b = id / CU_;
        int ch = d_unsel[b * CU_ + j];
        const float4* src = reinterpret_cast<const float4*>(x)
                            + ((size_t)(b * C_ + ch)) * (HW_ / 4);
        float4* dst = reinterpret_cast<float4*>(out)
                      + ((size_t)(b * OUTC_ + OC_ + j)) * (HW_ / 4);
        #pragma unroll 4
        for (int i = tid; i < HW_ / 4; i += 256) dst[i] = src[i];
        return;
    }

    // ---------- conv path ----------
    extern __shared__ char smc[];
    uint32_t* ws_hi = (uint32_t*)(smc + SM_WHI);
    uint32_t* ws_lo = (uint32_t*)(smc + SM_WLO);
    __nv_bfloat16* xs_hi = (__nv_bfloat16*)(smc + SM_XHI);
    __nv_bfloat16* xs_lo = (__nv_bfloat16*)(smc + SM_XLO);
    __shared__ int ssel[P_];
    __shared__ float sbias[OC_];

    const int cid = grp * 16 + (slot - 3);    // 0..2047
    const int b   = cid >> 8;
    const int rem = cid & 255;
    const int r0  = (rem >> 1) * 2;           // 2-row strip
    const int c0  = (rem & 1) * 128;

    if (tid < P_)  ssel[tid]  = d_sel[b * P_ + tid];
    if (tid < OC_) sbias[tid] = bias[tid];
    for (int i = tid; i < WS_U32; i += 256) { ws_hi[i] = d_whi[i]; ws_lo[i] = d_wlo[i]; }
    __syncthreads();                           // ssel ready

    // stage strip: 16 ch x 4 rows x 130 cols, bf16 hi/lo split, channel-minor
    for (int idx = tid; idx < 16 * 4 * 130; idx += 256) {
        int p   = idx / 520;
        int r2  = idx % 520;
        int rr  = r2 / 130;
        int col = r2 % 130;
        int gr = r0 + rr - 1, gc = c0 + col - 1;
        float v = 0.0f;
        if ((unsigned)gr < 256u && (unsigned)gc < 256u)
            v = x[(((size_t)(b * C_ + ssel[p])) << 16) + (gr << 8) + gc];
        __nv_bfloat16 hv = __float2bfloat16_rn(v);
        __nv_bfloat16 lv = __float2bfloat16_rn(v - __bfloat162float(hv));
        int hidx = (rr * 132 + col) * 18 + p;
        xs_hi[hidx] = hv;
        xs_lo[hidx] = lv;
    }
    __syncthreads();

    const int w  = tid >> 5, l = tid & 31;
    const int warpRow = w >> 2;               // 0 or 1
    const int lq = l >> 2, lr = l & 3;
    const uint32_t* xh_u = (const uint32_t*)xs_hi;
    const uint32_t* xl_u = (const uint32_t*)xs_lo;

    float acc[2][8][4];
    #pragma unroll
    for (int i2 = 0; i2 < 2; i2++)
        #pragma unroll
        for (int ni = 0; ni < 8; ni++)
            #pragma unroll
            for (int r = 0; r < 4; r++) acc[i2][ni][r] = 0.0f;

    #pragma unroll
    for (int chunk = 0; chunk < 9; chunk++) {
        const int kh = chunk / 3, kw = chunk % 3;
        // B fragments: b0 at p2=lr, b1 at p2=lr+4, n = ni*8 + lq (stride 72: bank-clean)
        uint32_t bh[8][2], bl[8][2];
        #pragma unroll
        for (int ni = 0; ni < 8; ni++) {
            int base = chunk * 576 + ni * 8 + lq;
            bh[ni][0] = ws_hi[base + lr * 72];
            bh[ni][1] = ws_hi[base + (lr + 4) * 72];
            bl[ni][0] = ws_lo[base + lr * 72];
            bl[ni][1] = ws_lo[base + (lr + 4) * 72];
        }
        #pragma unroll
        for (int mi2 = 0; mi2 < 2; mi2++) {
            const int colbase = (2 * (w & 3) + mi2) * 16;
            const int abase = ((warpRow + kh) * 132 + colbase + lq + kw) * 9 + lr;
            uint32_t ah[4], al[4];
            ah[0] = xh_u[abase];            al[0] = xl_u[abase];
            ah[1] = xh_u[abase + 72];       al[1] = xl_u[abase + 72];      // row +8 pixels
            ah[2] = xh_u[abase + 4];        al[2] = xl_u[abase + 4];       // k +8 channels
            ah[3] = xh_u[abase + 76];       al[3] = xl_u[abase + 76];
            #pragma unroll
            for (int ni = 0; ni < 8; ni++) mma_bf16(acc[mi2][ni], ah, bh[ni]);
            #pragma unroll
            for (int ni = 0; ni < 8; ni++) mma_bf16(acc[mi2][ni], ah, bl[ni]);
            #pragma unroll
            for (int ni = 0; ni < 8; ni++) mma_bf16(acc[mi2][ni], al, bh[ni]);
        }
    }

    // epilogue: bias + store. d0/d1: (pixel colbase+lq, oc0/oc0+1); d2/d3: pixel +8.
    const int gr = r0 + warpRow;
    #pragma unroll
    for (int mi2 = 0; mi2 < 2; mi2++) {
        const int pix = (2 * (w & 3) + mi2) * 16 + lq;
        #pragma unroll
        for (int ni = 0; ni < 8; ni++) {
            const int oc0 = ni * 8 + lr * 2;
            float* p0 = out + (((size_t)(b * OUTC_ + oc0)) << 16) + (gr << 8) + c0 + pix;
            float* p1 = p0 + HW_;
            p0[0] = acc[mi2][ni][0] + sbias[oc0];
            p1[0] = acc[mi2][ni][1] + sbias[oc0 + 1];
            p0[8] = acc[mi2][ni][2] + sbias[oc0];
            p1[8] = acc[mi2][ni][3] + sbias[oc0 + 1];
        }
    }
}

// ---------------- launch ----------------------------------------------------
extern "C" void kernel_launch(void* const* d_in, const int* in_sizes, int n_in,
                              void* d_out, int out_size) {
    (void)in_sizes; (void)n_in; (void)out_size;
    const float* x    = (const float*)d_in[0];
    const float* wgt  = (const float*)d_in[1];
    const float* bias = (const float*)d_in[2];
    float* out = (float*)d_out;

    cudaFuncSetAttribute(conv_copy_kernel,
                         cudaFuncAttributeMaxDynamicSharedMemorySize, SM_TOTAL);

    prep_W_kernel<<<1, 256>>>(wgt);
    channel_stats_kernel<<<B_ * C_, 1024>>>(x);
    topk_kernel<<<1, 8>>>();
    conv_copy_kernel<<<GRID_, 256, SM_TOTAL>>>(x, bias, out);
}

// round 12
// speedup vs baseline: 2.4678x; 1.5279x over previous
#include <cuda_runtime.h>
#include <cuda_bf16.h>
#include <cstdint>

// Problem constants
#define B_    8
#define C_    64
#define H_    256
#define W_    256
#define HW_   65536
#define OC_   64
#define P_    16
#define CU_   48
#define OUTC_ 112

// ---------------- device globals -------------------------------------------
__device__ float d_act[B_ * C_];
__device__ int   d_sel[B_ * P_];
__device__ int   d_unsel[B_ * CU_];
// packed weights: [chunk 9][p2 8][n pad 72] u32 = (bf16 p=2*p2, bf16 p=2*p2+1)
__device__ uint32_t d_whi[9 * 8 * 72];
__device__ uint32_t d_wlo[9 * 8 * 72];

// ---------------- kernel 0: weight split + fragment-layout pack -------------
__global__ void prep_W_kernel(const float* __restrict__ wgt) {
    for (int i = threadIdx.x; i < 9 * 8 * 72; i += 256) {
        int chunk = i / 576;
        int rem   = i % 576;
        int p2    = rem / 72;
        int n     = rem % 72;
        uint32_t hi = 0, lo = 0;
        if (n < 64) {
            float w0 = wgt[n * 144 + (2 * p2) * 9 + chunk];
            float w1 = wgt[n * 144 + (2 * p2 + 1) * 9 + chunk];
            __nv_bfloat16 h0 = __float2bfloat16_rn(w0);
            __nv_bfloat16 h1 = __float2bfloat16_rn(w1);
            __nv_bfloat16 l0 = __float2bfloat16_rn(w0 - __bfloat162float(h0));
            __nv_bfloat16 l1 = __float2bfloat16_rn(w1 - __bfloat162float(h1));
            hi = (uint32_t)__bfloat16_as_ushort(h0) | ((uint32_t)__bfloat16_as_ushort(h1) << 16);
            lo = (uint32_t)__bfloat16_as_ushort(l0) | ((uint32_t)__bfloat16_as_ushort(l1) << 16);
        }
        d_whi[i] = hi;
        d_wlo[i] = lo;
    }
}

// ---------------- kernel 1: per-channel min/max + histogram + entropy -------
// 32 per-warp histogram copies: no cross-warp atomic contention.
__global__ void __launch_bounds__(1024, 2)
channel_stats_kernel(const float* __restrict__ x) {
    const int bc  = blockIdx.x;
    const int tid = threadIdx.x;
    const int lane = tid & 31, wid = tid >> 5;
    const float4* xp = reinterpret_cast<const float4*>(x) + (size_t)bc * (HW_ / 4);

    float mn = 3.402823466e38f, mx = -3.402823466e38f;
    for (int i = tid; i < HW_ / 4; i += 1024) {
        float4 v = xp[i];
        mn = fminf(mn, fminf(fminf(v.x, v.y), fminf(v.z, v.w)));
        mx = fmaxf(mx, fmaxf(fmaxf(v.x, v.y), fmaxf(v.z, v.w)));
    }
    #pragma unroll
    for (int off = 16; off > 0; off >>= 1) {
        mn = fminf(mn, __shfl_xor_sync(0xffffffffu, mn, off));
        mx = fmaxf(mx, __shfl_xor_sync(0xffffffffu, mx, off));
    }
    __shared__ float smn[32], smx[32];
    __shared__ float s_mn, s_rng, s_scale;
    if (lane == 0) { smn[wid] = mn; smx[wid] = mx; }
    __syncthreads();
    if (tid == 0) {
        float m = smn[0], M = smx[0];
        #pragma unroll
        for (int i = 1; i < 32; i++) { m = fminf(m, smn[i]); M = fmaxf(M, smx[i]); }
        s_mn = m;
        float rng = __fadd_rn(__fsub_rn(M, m), 1e-8f);
        s_rng = rng;
        s_scale = __fdiv_rn(256.0f, rng);
    }
    __syncthreads();

    __shared__ int h[32][256];
    for (int i = tid; i < 32 * 256; i += 1024) ((int*)h)[i] = 0;
    __syncthreads();
    const float mnv = s_mn, rng = s_rng, sc = s_scale;
    int* hw = h[wid];
    for (int i = tid; i < HW_ / 4; i += 1024) {
        float4 v = xp[i];
        float vals[4] = { v.x, v.y, v.z, v.w };
        #pragma unroll
        for (int k = 0; k < 4; k++) {
            float t = __fsub_rn(vals[k], mnv);
            float a = __fmul_rn(t, sc);
            int bin = (int)a;
            float fr = a - (float)bin;
            float band = __fmaf_rn(4e-7f, a, 1e-6f);
            if (fr < band || fr > 1.0f - band) {
                a = __fmul_rn(__fdiv_rn(t, rng), 256.0f);   // exact path near edges
                bin = (int)a;
            }
            if (bin > 255) bin = 255;
            atomicAdd(&hw[bin], 1);
        }
    }
    __syncthreads();

    __shared__ float hf[256], red[256];
    if (tid < 256) {
        int c = 0;
        #pragma unroll
        for (int w2 = 0; w2 < 32; w2++) c += h[w2][tid];
        hf[tid] = (float)c + 1e-8f;
        red[tid] = hf[tid];
    }
    __syncthreads();
    for (int st = 128; st > 0; st >>= 1) {
        if (tid < st) red[tid] += red[tid + st];
        __syncthreads();
    }
    __shared__ float s_tot;
    if (tid == 0) s_tot = red[0];
    __syncthreads();
    if (tid < 256) {
        float p = hf[tid] / s_tot;
        red[tid] = p * logf(p + 1e-8f);
    }
    __syncthreads();
    for (int st = 128; st > 0; st >>= 1) {
        if (tid < st) red[tid] += red[tid + st];
        __syncthreads();
    }
    if (tid == 0) d_act[bc] = -red[0];
}

// ---------------- kernel 2: top-16 + unselected -----------------------------
__global__ void topk_kernel() {
    int b = threadIdx.x;
    if (b >= B_) return;
    float a[C_];
    bool  m[C_];
    for (int c = 0; c < C_; c++) { a[c] = d_act[b * C_ + c]; m[c] = false; }
    for (int k = 0; k < P_; k++) {
        float best = -3.402823466e38f;
        int bi = 0;
        for (int c = 0; c < C_; c++)
            if (!m[c] && a[c] > best) { best = a[c]; bi = c; }
        d_sel[b * P_ + k] = bi;
        m[bi] = true;
    }
    int j = 0;
    for (int c = 0; c < C_; c++)
        if (!m[c]) d_unsel[b * CU_ + (j++)] = c;
}

// ---------------- kernel 3 (fused): mma.sync bf16x3 conv + untouched copy ---
// Same structure as round 10, but reg-capped for 2 CTAs/SM (bl loaded inline).
#define WS_U32   (9 * 8 * 72)                 // 5184 u32 per blob
#define XS_HALF  (4 * 132 * 18)               // 9504 halves per blob
#define SM_WHI   0
#define SM_WLO   (WS_U32 * 4)                 // 20736
#define SM_XHI   (2 * WS_U32 * 4)             // 41472
#define SM_XLO   (SM_XHI + XS_HALF * 2)       // 60480
#define SM_TOTAL (SM_XLO + XS_HALF * 2)       // 79488

#define NCONV 2048
#define NCOPY (B_ * CU_)                      // 384
#define GRID_ (NCONV + NCOPY)                 // 2432 = 128 * 19

__device__ __forceinline__ void mma_bf16(float* d, const uint32_t* a, const uint32_t* b) {
    asm volatile(
        "mma.sync.aligned.m16n8k16.row.col.f32.bf16.bf16.f32 "
        "{%0,%1,%2,%3}, {%4,%5,%6,%7}, {%8,%9}, {%0,%1,%2,%3};\n"
        : "+f"(d[0]), "+f"(d[1]), "+f"(d[2]), "+f"(d[3])
        : "r"(a[0]), "r"(a[1]), "r"(a[2]), "r"(a[3]), "r"(b[0]), "r"(b[1]));
}

__global__ void __launch_bounds__(256, 2)
conv_copy_kernel(const float* __restrict__ x, const float* __restrict__ bias,
                 float* __restrict__ out) {
    const int tid  = threadIdx.x;
    const int grp  = blockIdx.x / 19;
    const int slot = blockIdx.x % 19;

    // ---------- copy path (3 of every 19 blocks) ----------
    if (slot < 3) {
        int id = grp * 3 + slot;              // 0..383
        int j = id % CU_, b = id / CU_;
        int ch = d_unsel[b * CU_ + j];
        const float4* src = reinterpret_cast<const float4*>(x)
                            + ((size_t)(b * C_ + ch)) * (HW_ / 4);
        float4* dst = reinterpret_cast<float4*>(out)
                      + ((size_t)(b * OUTC_ + OC_ + j)) * (HW_ / 4);
        #pragma unroll 4
        for (int i = tid; i < HW_ / 4; i += 256) dst[i] = src[i];
        return;
    }

    // ---------- conv path ----------
    extern __shared__ char smc[];
    uint32_t* ws_hi = (uint32_t*)(smc + SM_WHI);
    uint32_t* ws_lo = (uint32_t*)(smc + SM_WLO);
    __nv_bfloat16* xs_hi = (__nv_bfloat16*)(smc + SM_XHI);
    __nv_bfloat16* xs_lo = (__nv_bfloat16*)(smc + SM_XLO);
    __shared__ int ssel[P_];
    __shared__ float sbias[OC_];

    const int cid = grp * 16 + (slot - 3);    // 0..2047
    const int b   = cid >> 8;
    const int rem = cid & 255;
    const int r0  = (rem >> 1) * 2;           // 2-row strip
    const int c0  = (rem & 1) * 128;

    if (tid < P_)  ssel[tid]  = d_sel[b * P_ + tid];
    if (tid < OC_) sbias[tid] = bias[tid];
    for (int i = tid; i < WS_U32; i += 256) { ws_hi[i] = d_whi[i]; ws_lo[i] = d_wlo[i]; }
    __syncthreads();                           // ssel ready

    // stage strip: 16 ch x 4 rows x 130 cols, bf16 hi/lo split, channel-minor
    for (int idx = tid; idx < 16 * 4 * 130; idx += 256) {
        int p   = idx / 520;
        int r2  = idx % 520;
        int rr  = r2 / 130;
        int col = r2 % 130;
        int gr = r0 + rr - 1, gc = c0 + col - 1;
        float v = 0.0f;
        if ((unsigned)gr < 256u && (unsigned)gc < 256u)
            v = x[(((size_t)(b * C_ + ssel[p])) << 16) + (gr << 8) + gc];
        __nv_bfloat16 hv = __float2bfloat16_rn(v);
        __nv_bfloat16 lv = __float2bfloat16_rn(v - __bfloat162float(hv));
        int hidx = (rr * 132 + col) * 18 + p;
        xs_hi[hidx] = hv;
        xs_lo[hidx] = lv;
    }
    __syncthreads();

    const int w  = tid >> 5, l = tid & 31;
    const int warpRow = w >> 2;               // 0 or 1
    const int lq = l >> 2, lr = l & 3;
    const uint32_t* xh_u = (const uint32_t*)xs_hi;
    const uint32_t* xl_u = (const uint32_t*)xs_lo;

    float acc[2][8][4];
    #pragma unroll
    for (int i2 = 0; i2 < 2; i2++)
        #pragma unroll
        for (int ni = 0; ni < 8; ni++)
            #pragma unroll
            for (int r = 0; r < 4; r++) acc[i2][ni][r] = 0.0f;

    #pragma unroll
    for (int chunk = 0; chunk < 9; chunk++) {
        const int kh = chunk / 3, kw = chunk % 3;
        // cache only bh (used twice); bl loaded inline to cut 16 regs
        uint32_t bh[8][2];
        #pragma unroll
        for (int ni = 0; ni < 8; ni++) {
            int base = chunk * 576 + ni * 8 + lq;
            bh[ni][0] = ws_hi[base + lr * 72];
            bh[ni][1] = ws_hi[base + (lr + 4) * 72];
        }
        #pragma unroll
        for (int mi2 = 0; mi2 < 2; mi2++) {
            const int colbase = (2 * (w & 3) + mi2) * 16;
            const int abase = ((warpRow + kh) * 132 + colbase + lq + kw) * 9 + lr;
            uint32_t ah[4], al[4];
            ah[0] = xh_u[abase];            al[0] = xl_u[abase];
            ah[1] = xh_u[abase + 72];       al[1] = xl_u[abase + 72];      // row +8 pixels
            ah[2] = xh_u[abase + 4];        al[2] = xl_u[abase + 4];       // k +8 channels
            ah[3] = xh_u[abase + 76];       al[3] = xl_u[abase + 76];
            #pragma unroll
            for (int ni = 0; ni < 8; ni++) mma_bf16(acc[mi2][ni], ah, bh[ni]);
            #pragma unroll
            for (int ni = 0; ni < 8; ni++) {
                int base = chunk * 576 + ni * 8 + lq;
                uint32_t bl[2];
                bl[0] = ws_lo[base + lr * 72];
                bl[1] = ws_lo[base + (lr + 4) * 72];
                mma_bf16(acc[mi2][ni], ah, bl);
            }
            #pragma unroll
            for (int ni = 0; ni < 8; ni++) mma_bf16(acc[mi2][ni], al, bh[ni]);
        }
    }

    // epilogue: bias + store
    const int gr = r0 + warpRow;
    #pragma unroll
    for (int mi2 = 0; mi2 < 2; mi2++) {
        const int pix = (2 * (w & 3) + mi2) * 16 + lq;
        #pragma unroll
        for (int ni = 0; ni < 8; ni++) {
            const int oc0 = ni * 8 + lr * 2;
            float* p0 = out + (((size_t)(b * OUTC_ + oc0)) << 16) + (gr << 8) + c0 + pix;
            float* p1 = p0 + HW_;
            p0[0] = acc[mi2][ni][0] + sbias[oc0];
            p1[0] = acc[mi2][ni][1] + sbias[oc0 + 1];
            p0[8] = acc[mi2][ni][2] + sbias[oc0];
            p1[8] = acc[mi2][ni][3] + sbias[oc0 + 1];
        }
    }
}

// ---------------- launch ----------------------------------------------------
extern "C" void kernel_launch(void* const* d_in, const int* in_sizes, int n_in,
                              void* d_out, int out_size) {
    (void)in_sizes; (void)n_in; (void)out_size;
    const float* x    = (const float*)d_in[0];
    const float* wgt  = (const float*)d_in[1];
    const float* bias = (const float*)d_in[2];
    float* out = (float*)d_out;

    cudaFuncSetAttribute(conv_copy_kernel,
                         cudaFuncAttributeMaxDynamicSharedMemorySize, SM_TOTAL);
    cudaFuncSetAttribute(conv_copy_kernel,
                         cudaFuncAttributePreferredSharedMemoryCarveout, 100);

    prep_W_kernel<<<1, 256>>>(wgt);
    channel_stats_kernel<<<B_ * C_, 1024>>>(x);
    topk_kernel<<<1, 8>>>();
    conv_copy_kernel<<<GRID_, 256, SM_TOTAL>>>(x, bias, out);
}